// round 13
// baseline (speedup 1.0000x reference)
#include <cuda_runtime.h>
#include <cuda_fp16.h>
#include <cstdint>

#define BATCH 16
#define HW    4096
#define C     256
#define D     32
#define DV    128
#define M_TOTAL (BATCH * HW)

#define TQ 128
#define TK 128
#define NTILES (HW / TK)
#define LOG2E 1.4426950408889634f

#define KROW 20     // attn K smem row stride (u32)
#define VROW 68     // attn V smem row stride (u32)
#define BUFB 55296  // attn smem bytes per buffer (Kh 10240 + Kl 10240 + V 34816)

// ---- device scratch (no allocation allowed) ----
__device__ __align__(16) __half d_xh [(size_t)M_TOTAL * C];   // x hi
__device__ __align__(16) __half d_xl [(size_t)M_TOTAL * C];   // x lo
__device__ __align__(16) __half d_wph[192 * C];               // proj W hi [n][k]
__device__ __align__(16) __half d_wpl[192 * C];               // proj W lo [n][k]
__device__ __align__(16) __half d_woh[C * DV];                // Wo hi [n][k]
__device__ __align__(16) __half d_wol[C * DV];                // Wo lo [n][k]
__device__ __align__(16) __half d_fh [(size_t)M_TOTAL * D];   // K hi
__device__ __align__(16) __half d_fl [(size_t)M_TOTAL * D];   // K lo
__device__ float                d_g  [(size_t)M_TOTAL * D];   // Q fp32
__device__ __align__(16) __half d_hn [(size_t)M_TOTAL * DV];  // V fp16 [m][dv]
__device__ __align__(16) __half d_obh[(size_t)M_TOTAL * DV];  // O hi
__device__ __align__(16) __half d_obl[(size_t)M_TOTAL * DV];  // O lo

// ---- helpers ----
__device__ __forceinline__ uint32_t packh2(float lo, float hi) {
    uint32_t r;
    asm("cvt.rn.f16x2.f32 %0, %1, %2;" : "=r"(r) : "f"(hi), "f"(lo));
    return r;
}
__device__ __forceinline__ void split2(float v0, float v1, uint32_t& hi, uint32_t& lo) {
    hi = packh2(v0, v1);
    __half2 h = *reinterpret_cast<__half2*>(&hi);
    float2 f = __half22float2(h);
    lo = packh2(v0 - f.x, v1 - f.y);
}
__device__ __forceinline__ void mma16816(float* c, const uint32_t* a,
                                         uint32_t b0, uint32_t b1) {
    asm volatile(
        "mma.sync.aligned.m16n8k16.row.col.f32.f16.f16.f32 "
        "{%0,%1,%2,%3}, {%4,%5,%6,%7}, {%8,%9}, {%0,%1,%2,%3};"
        : "+f"(c[0]), "+f"(c[1]), "+f"(c[2]), "+f"(c[3])
        : "r"(a[0]), "r"(a[1]), "r"(a[2]), "r"(a[3]), "r"(b0), "r"(b1));
}
__device__ __forceinline__ void cp16(uint32_t sdst, const void* gsrc) {
    asm volatile("cp.async.cg.shared.global [%0], [%1], 16;" :: "r"(sdst), "l"(gsrc));
}
__device__ __forceinline__ void ldsm4(uint32_t* r, uint32_t a) {
    asm volatile("ldmatrix.sync.aligned.m8n8.x4.shared.b16 {%0,%1,%2,%3}, [%4];"
                 : "=r"(r[0]), "=r"(r[1]), "=r"(r[2]), "=r"(r[3]) : "r"(a));
}
__device__ __forceinline__ void ldsm4t(uint32_t* r, uint32_t a) {
    asm volatile("ldmatrix.sync.aligned.m8n8.x4.trans.shared.b16 {%0,%1,%2,%3}, [%4];"
                 : "=r"(r[0]), "=r"(r[1]), "=r"(r[2]), "=r"(r[3]) : "r"(a));
}

// ---------------------------------------------------------------------------
// Pre-split: x -> fp16 hi/lo
// ---------------------------------------------------------------------------
__global__ __launch_bounds__(256) void presplit_x_kernel(const float* __restrict__ x) {
    const size_t NX4 = (size_t)M_TOTAL * C / 4;
    const size_t stride = (size_t)gridDim.x * blockDim.x;
    for (size_t i = (size_t)blockIdx.x * blockDim.x + threadIdx.x; i < NX4; i += stride) {
        float4 v = ((const float4*)x)[i];
        uint32_t h0, l0, h1, l1;
        split2(v.x, v.y, h0, l0);
        split2(v.z, v.w, h1, l1);
        ((uint2*)d_xh)[i] = make_uint2(h0, h1);
        ((uint2*)d_xl)[i] = make_uint2(l0, l1);
    }
}

__global__ __launch_bounds__(256) void presplit_w_kernel(
    const float* __restrict__ Wf, const float* __restrict__ Wg,
    const float* __restrict__ Wh, const float* __restrict__ Wo)
{
    const int t = blockIdx.x * blockDim.x + threadIdx.x;
    if (t < 192 * 256) {
        const int n = t >> 8, k = t & 255;
        const float v = (n < 32) ? Wf[k * 32 + n]
                      : (n < 64) ? Wg[k * 32 + (n - 32)]
                                 : Wh[k * 128 + (n - 64)];
        const __half hv = __float2half_rn(v);
        d_wph[t] = hv;
        d_wpl[t] = __float2half_rn(v - __half2float(hv));
    }
    const int t2 = t - 192 * 256;
    if (t2 >= 0 && t2 < 256 * 128) {
        const int n = t2 >> 7, k = t2 & 127;
        const float v = Wo[k * 256 + n];
        const __half hv = __float2half_rn(v);
        d_woh[t2] = hv;
        d_wol[t2] = __float2half_rn(v - __half2float(hv));
    }
}

// ---------------------------------------------------------------------------
// Flash attention: 64-key subtiles, PV deferred one subtile and hand-
// interleaved with the next subtile's softmax chain. Triple-buffered cp.async.
// ---------------------------------------------------------------------------
__global__ __launch_bounds__(256, 1) void attn_kernel() {
    extern __shared__ char sm[];
    const uint32_t smem_u32 = (uint32_t)__cvta_generic_to_shared(sm);

    const int b   = blockIdx.y;
    const int q0  = blockIdx.x * TQ;
    const int tid = threadIdx.x;
    const int w   = tid >> 5;
    const int lane = tid & 31;
    const int lr  = lane >> 2;
    const int lc  = lane & 3;

    // Q fragments (fp16 hi/lo, pre-scaled by log2e)
    uint32_t qh[2][4], ql[2][4];
    {
        const float* gq = d_g + ((size_t)b * HW + q0 + w * 16) * D;
        #pragma unroll
        for (int ks = 0; ks < 2; ks++) {
            #pragma unroll
            for (int r = 0; r < 4; r++) {
                const int row = (r & 1) ? (lr + 8) : lr;
                const int col = ks * 16 + ((r & 2) ? 8 : 0) + 2 * lc;
                const float v0 = gq[row * D + col]     * LOG2E;
                const float v1 = gq[row * D + col + 1] * LOG2E;
                split2(v0, v1, qh[ks][r], ql[ks][r]);
            }
        }
    }

    float o[16][4];
    #pragma unroll
    for (int nt = 0; nt < 16; nt++)
        o[nt][0] = o[nt][1] = o[nt][2] = o[nt][3] = 0.f;
    float lsum[4] = {0.f, 0.f, 0.f, 0.f};
    float mrow0 = -1e30f, mrow1 = -1e30f;

    auto issue_tile = [&](int t) {
        const uint32_t sb = smem_u32 + (t % 3) * BUFB;
        const int k0 = t * TK;
        #pragma unroll
        for (int i = 0; i < 4; i++) {                  // K hi+lo
            const int idx = tid + 256 * i;
            const int arr = idx >> 9;
            const int row = (idx >> 2) & 127;
            const int c   = idx & 3;
            const __half* g = (arr ? d_fl : d_fh)
                              + ((size_t)(b * HW + k0 + row)) * D + c * 8;
            cp16(sb + arr * 10240 + row * 80 + c * 16, g);
        }
        #pragma unroll
        for (int i = 0; i < 8; i++) {                  // V rows
            const int idx = tid + 256 * i;
            const int row = idx >> 4;
            const int c   = idx & 15;
            const __half* g = d_hn + ((size_t)(b * HW + k0 + row)) * DV + c * 8;
            cp16(sb + 20480 + row * 272 + c * 16, g);
        }
        asm volatile("cp.async.commit_group;");
    };

    const uint32_t koff = ((lane & 7) * KROW + (lane >> 3) * 4) * 4;
    const uint32_t voff = ((lane & 15) * VROW) * 4 + (lane >> 4) * 16;

    uint32_t paA[4][4], paB[4][4];
    uint32_t vprev = 0;
    const uint32_t ONES = 0x3C003C00u;

    // S GEMM for one 64-key subtile
    auto sub_S = [&](uint32_t sb, int st, float (&s)[8][4]) {
        const uint32_t khb = sb + koff + st * 5120;
        #pragma unroll
        for (int nt = 0; nt < 8; nt++) {
            uint32_t kh[4], kl[4];
            ldsm4(kh, khb + nt * 640);
            ldsm4(kl, khb + 10240 + nt * 640);
            s[nt][0] = s[nt][1] = s[nt][2] = s[nt][3] = 0.f;
            mma16816(s[nt], qh[0], kh[0], kh[1]);
            mma16816(s[nt], ql[0], kh[0], kh[1]);
            mma16816(s[nt], qh[0], kl[0], kl[1]);
            mma16816(s[nt], qh[1], kh[2], kh[3]);
            mma16816(s[nt], ql[1], kh[2], kh[3]);
            mma16816(s[nt], qh[1], kl[2], kl[3]);
        }
    };

    // one ks-step of the deferred PV (17 HMMA + 8 LDSM)
    auto pv_ks = [&](const uint32_t (&pap)[4][4], int ks) {
        mma16816(lsum, pap[ks], ONES, ONES);
        const uint32_t vrow = vprev + ks * 4352;
        #pragma unroll
        for (int ntp = 0; ntp < 8; ntp++) {
            uint32_t v[4];
            ldsm4t(v, vrow + ntp * 32);
            mma16816(o[2 * ntp],     pap[ks], v[0], v[1]);
            mma16816(o[2 * ntp + 1], pap[ks], v[2], v[3]);
        }
    };

    // subtile with deferred PV of the previous subtile, hand-interleaved
    auto subtile_full = [&](uint32_t sb, int st,
                            uint32_t (&pac)[4][4], const uint32_t (&pap)[4][4]) {
        float s[8][4];
        sub_S(sb, st, s);

        float mx0 = fmaxf(s[0][0], s[0][1]);
        float mx1 = fmaxf(s[0][2], s[0][3]);
        #pragma unroll
        for (int nt = 1; nt < 8; nt++) {
            mx0 = fmaxf(mx0, fmaxf(s[nt][0], s[nt][1]));
            mx1 = fmaxf(mx1, fmaxf(s[nt][2], s[nt][3]));
        }
        pv_ks(pap, 0);                                   // fills shfl latency
        mx0 = fmaxf(mx0, __shfl_xor_sync(0xffffffffu, mx0, 1));
        mx0 = fmaxf(mx0, __shfl_xor_sync(0xffffffffu, mx0, 2));
        mx1 = fmaxf(mx1, __shfl_xor_sync(0xffffffffu, mx1, 1));
        mx1 = fmaxf(mx1, __shfl_xor_sync(0xffffffffu, mx1, 2));
        pv_ks(pap, 1);
        const float mn0 = fmaxf(mrow0, mx0);
        const float mn1 = fmaxf(mrow1, mx1);
        const float corr0 = exp2f(mrow0 - mn0);
        const float corr1 = exp2f(mrow1 - mn1);
        mrow0 = mn0; mrow1 = mn1;
        pv_ks(pap, 2);
        #pragma unroll
        for (int nt = 0; nt < 8; nt++) {
            const uint32_t d01 = packh2(s[nt][0] - mn0, s[nt][1] - mn0);
            const uint32_t d23 = packh2(s[nt][2] - mn1, s[nt][3] - mn1);
            uint32_t p01, p23;
            asm("ex2.approx.f16x2 %0, %1;" : "=r"(p01) : "r"(d01));
            asm("ex2.approx.f16x2 %0, %1;" : "=r"(p23) : "r"(d23));
            pac[nt >> 1][(nt & 1) ? 2 : 0] = p01;
            pac[nt >> 1][(nt & 1) ? 3 : 1] = p23;
        }
        pv_ks(pap, 3);
        // junction: rescale state into the new max frame
        lsum[0] *= corr0; lsum[2] *= corr1;
        #pragma unroll
        for (int nt = 0; nt < 16; nt++) {
            o[nt][0] *= corr0; o[nt][1] *= corr0;
            o[nt][2] *= corr1; o[nt][3] *= corr1;
        }
        vprev = sb + 20480 + voff + st * 4 * 4352;
    };

    // first subtile: no deferred PV (o = 0, lsum = 0)
    auto subtile_first = [&](uint32_t sb, uint32_t (&pac)[4][4]) {
        float s[8][4];
        sub_S(sb, 0, s);
        float mx0 = fmaxf(s[0][0], s[0][1]);
        float mx1 = fmaxf(s[0][2], s[0][3]);
        #pragma unroll
        for (int nt = 1; nt < 8; nt++) {
            mx0 = fmaxf(mx0, fmaxf(s[nt][0], s[nt][1]));
            mx1 = fmaxf(mx1, fmaxf(s[nt][2], s[nt][3]));
        }
        mx0 = fmaxf(mx0, __shfl_xor_sync(0xffffffffu, mx0, 1));
        mx0 = fmaxf(mx0, __shfl_xor_sync(0xffffffffu, mx0, 2));
        mx1 = fmaxf(mx1, __shfl_xor_sync(0xffffffffu, mx1, 1));
        mx1 = fmaxf(mx1, __shfl_xor_sync(0xffffffffu, mx1, 2));
        mrow0 = mx0; mrow1 = mx1;
        #pragma unroll
        for (int nt = 0; nt < 8; nt++) {
            const uint32_t d01 = packh2(s[nt][0] - mx0, s[nt][1] - mx0);
            const uint32_t d23 = packh2(s[nt][2] - mx1, s[nt][3] - mx1);
            uint32_t p01, p23;
            asm("ex2.approx.f16x2 %0, %1;" : "=r"(p01) : "r"(d01));
            asm("ex2.approx.f16x2 %0, %1;" : "=r"(p23) : "r"(d23));
            pac[nt >> 1][(nt & 1) ? 2 : 0] = p01;
            pac[nt >> 1][(nt & 1) ? 3 : 1] = p23;
        }
        vprev = sb + 20480 + voff;   // st = 0
    };

    // ---- pipeline ----
    issue_tile(0);
    issue_tile(1);
    asm volatile("cp.async.wait_group 1;");
    __syncthreads();

    subtile_first(smem_u32, paA);          // (t=0, st=0) -> paA
    __syncthreads();
    issue_tile(2);
    subtile_full(smem_u32, 1, paB, paA);   // (0,1): PV(0,0)

    #pragma unroll 1
    for (int t = 1; t < NTILES; t++) {
        if (t + 1 < NTILES) asm volatile("cp.async.wait_group 1;");
        else                asm volatile("cp.async.wait_group 0;");
        __syncthreads();
        const uint32_t sb = smem_u32 + (t % 3) * BUFB;
        subtile_full(sb, 0, paA, paB);     // (t,0): PV(t-1,1) reads buf t-1
        __syncthreads();                   // all warps done with buf t-1's V
        if (t + 2 < NTILES) issue_tile(t + 2);
        subtile_full(sb, 1, paB, paA);     // (t,1): PV(t,0)
    }

    // drain final PV (NTILES-1, st=1) held in paB
    #pragma unroll
    for (int ks = 0; ks < 4; ks++) pv_ks(paB, ks);

    // ---- normalize + store fp16 hi/lo ----
    const float inv0 = 1.f / lsum[0];
    const float inv1 = 1.f / lsum[2];
    uint32_t* goh = (uint32_t*)d_obh + ((size_t)b * HW + q0 + w * 16) * 64;
    uint32_t* gol = (uint32_t*)d_obl + ((size_t)b * HW + q0 + w * 16) * 64;
    #pragma unroll
    for (int nt = 0; nt < 16; nt++) {
        uint32_t hi, lo;
        split2(o[nt][0] * inv0, o[nt][1] * inv0, hi, lo);
        goh[lr * 64 + nt * 4 + lc] = hi;
        gol[lr * 64 + nt * 4 + lc] = lo;
        split2(o[nt][2] * inv1, o[nt][3] * inv1, hi, lo);
        goh[(lr + 8) * 64 + nt * 4 + lc] = hi;
        gol[(lr + 8) * 64 + nt * 4 + lc] = lo;
    }
}

// ---------------------------------------------------------------------------
// proj: [65536,256] @ [256,192], fp16 3-term split, cp.async double-buffered.
// ---------------------------------------------------------------------------
#define PBUF 30720
__global__ __launch_bounds__(256, 2) void proj_kernel(
    const float* __restrict__ bf, const float* __restrict__ bg,
    const float* __restrict__ bh)
{
    extern __shared__ char smp[];
    const uint32_t sb0 = (uint32_t)__cvta_generic_to_shared(smp);

    const int m0 = blockIdx.x * 128;
    const int by = blockIdx.y;
    const int n0 = by * 64;
    const int tid = threadIdx.x;
    const int lane = tid & 31;
    const int w = tid >> 5;
    const int warpM = (w >> 1) * 32;
    const int warpN = (w & 1) * 32;
    const int lr = lane >> 2, lc = lane & 3;

    auto issue = [&](int s) {
        const uint32_t sb = sb0 + (s & 1) * PBUF;
        const int k0 = s * 32;
        #pragma unroll
        for (int i = 0; i < 4; i++) {
            const int idx = tid + 256 * i;
            const int arr = idx >> 9;
            const int row = (idx >> 2) & 127;
            const int c   = idx & 3;
            const __half* g = (arr ? d_xl : d_xh) + (size_t)(m0 + row) * C + k0 + c * 8;
            cp16(sb + arr * 10240 + row * 80 + c * 16, g);
        }
        #pragma unroll
        for (int i = 0; i < 2; i++) {
            const int idx = tid + 256 * i;
            const int arr = idx >> 8;
            const int row = (idx >> 2) & 63;
            const int c   = idx & 3;
            const __half* g = (arr ? d_wpl : d_wph) + (size_t)(n0 + row) * C + k0 + c * 8;
            cp16(sb + 20480 + arr * 5120 + row * 80 + c * 16, g);
        }
        asm volatile("cp.async.commit_group;");
    };

    float cfr[2][4][4];
    #pragma unroll
    for (int mt = 0; mt < 2; mt++)
        #pragma unroll
        for (int nt = 0; nt < 4; nt++)
            cfr[mt][nt][0] = cfr[mt][nt][1] = cfr[mt][nt][2] = cfr[mt][nt][3] = 0.f;

    issue(0); issue(1);

    #pragma unroll 1
    for (int s = 0; s < 8; s++) {
        if (s < 7) asm volatile("cp.async.wait_group 1;");
        else       asm volatile("cp.async.wait_group 0;");
        __syncthreads();

        const uint32_t sb = sb0 + (s & 1) * PBUF;

        uint32_t bhf[4][4], blf[4][4];
        #pragma unroll
        for (int g = 0; g < 4; g++) {
            const uint32_t base = sb + 20480 +
                ((warpN + g * 8 + (lane & 7)) * KROW + (lane >> 3) * 4) * 4;
            ldsm4(bhf[g], base);
            ldsm4(blf[g], base + 5120);
        }
        #pragma unroll
        for (int kf = 0; kf < 2; kf++) {
            uint32_t ah[2][4], al[2][4];
            #pragma unroll
            for (int mt = 0; mt < 2; mt++) {
                const uint32_t off = sb +
                    ((warpM + mt * 16 + (lane & 15)) * KROW + kf * 8 + (lane >> 4) * 4) * 4;
                ldsm4(ah[mt], off);
                ldsm4(al[mt], off + 10240);
            }
            #pragma unroll
            for (int mt = 0; mt < 2; mt++)
                #pragma unroll
                for (int nt = 0; nt < 4; nt++) {
                    const uint32_t b0 = bhf[nt][kf * 2], b1 = bhf[nt][kf * 2 + 1];
                    const uint32_t c0 = blf[nt][kf * 2], c1 = blf[nt][kf * 2 + 1];
                    mma16816(cfr[mt][nt], ah[mt], b0, b1);
                    mma16816(cfr[mt][nt], al[mt], b0, b1);
                    mma16816(cfr[mt][nt], ah[mt], c0, c1);
                }
        }
        __syncthreads();
        if (s + 2 < 8) issue(s + 2);
    }

    #pragma unroll
    for (int mt = 0; mt < 2; mt++) {
        const size_t mA = (size_t)(m0 + warpM + mt * 16 + lr);
        const size_t mB = mA + 8;
        #pragma unroll
        for (int nt = 0; nt < 4; nt++) {
            const int jl = warpN + nt * 8 + 2 * lc;
            const float c0 = cfr[mt][nt][0], c1 = cfr[mt][nt][1];
            const float c2 = cfr[mt][nt][2], c3 = cfr[mt][nt][3];
            if (by == 0) {
                if (jl < 32) {
                    const float b0v = bf[jl], b1v = bf[jl + 1];
                    uint32_t hi, lo;
                    split2(c0 + b0v, c1 + b1v, hi, lo);
                    ((uint32_t*)d_fh)[mA * 16 + (jl >> 1)] = hi;
                    ((uint32_t*)d_fl)[mA * 16 + (jl >> 1)] = lo;
                    split2(c2 + b0v, c3 + b1v, hi, lo);
                    ((uint32_t*)d_fh)[mB * 16 + (jl >> 1)] = hi;
                    ((uint32_t*)d_fl)[mB * 16 + (jl >> 1)] = lo;
                } else {
                    const int jj = jl - 32;
                    const float b0v = bg[jj], b1v = bg[jj + 1];
                    *(float2*)&d_g[mA * D + jj] = make_float2(c0 + b0v, c1 + b1v);
                    *(float2*)&d_g[mB * D + jj] = make_float2(c2 + b0v, c3 + b1v);
                }
            } else {
                const int dv = (by - 1) * 64 + jl;
                const float b0v = bh[dv], b1v = bh[dv + 1];
                ((uint32_t*)d_hn)[mA * 64 + (dv >> 1)] = packh2(c0 + b0v, c1 + b1v);
                ((uint32_t*)d_hn)[mB * 64 + (dv >> 1)] = packh2(c2 + b0v, c3 + b1v);
            }
        }
    }
}

// ---------------------------------------------------------------------------
// outproj: out = x + O @ Wo + bo, fp16 3-term, fully double-buffered.
// ---------------------------------------------------------------------------
#define OBUF 40960
__global__ __launch_bounds__(256, 1) void outproj_kernel(
    const float* __restrict__ x,
    const float* __restrict__ bo,
    float* __restrict__ out)
{
    extern __shared__ char smo[];
    const uint32_t sb0 = (uint32_t)__cvta_generic_to_shared(smo);

    const int m0 = blockIdx.x * 128;
    const int n0 = blockIdx.y * 128;
    const int tid = threadIdx.x;
    const int lane = tid & 31;
    const int w = tid >> 5;
    const int warpM = (w >> 2) * 64;
    const int warpN = (w & 3) * 32;
    const int lr = lane >> 2, lc = lane & 3;

    auto issue = [&](int s) {
        const uint32_t sb = sb0 + (s & 1) * OBUF;
        const int k0 = s * 32;
        #pragma unroll
        for (int i = 0; i < 4; i++) {
            const int idx = tid + 256 * i;
            const int arr = idx >> 9;
            const int row = (idx >> 2) & 127;
            const int c   = idx & 3;
            const __half* g = (arr ? d_obl : d_obh) + (size_t)(m0 + row) * DV + k0 + c * 8;
            cp16(sb + arr * 10240 + row * 80 + c * 16, g);
        }
        #pragma unroll
        for (int i = 0; i < 4; i++) {
            const int idx = tid + 256 * i;
            const int arr = idx >> 9;
            const int row = (idx >> 2) & 127;
            const int c   = idx & 3;
            const __half* g = (arr ? d_wol : d_woh) + (size_t)(n0 + row) * DV + k0 + c * 8;
            cp16(sb + 20480 + arr * 10240 + row * 80 + c * 16, g);
        }
        asm volatile("cp.async.commit_group;");
    };

    float cfr[4][4][4];
    #pragma unroll
    for (int mt = 0; mt < 4; mt++)
        #pragma unroll
        for (int nt = 0; nt < 4; nt++)
            cfr[mt][nt][0] = cfr[mt][nt][1] = cfr[mt][nt][2] = cfr[mt][nt][3] = 0.f;

    issue(0); issue(1);

    #pragma unroll 1
    for (int s = 0; s < 4; s++) {
        if (s < 3) asm volatile("cp.async.wait_group 1;");
        else       asm volatile("cp.async.wait_group 0;");
        __syncthreads();

        const uint32_t sb = sb0 + (s & 1) * OBUF;

        uint32_t bhf[4][4], blf[4][4];
        #pragma unroll
        for (int g = 0; g < 4; g++) {
            const uint32_t base = sb + 20480 +
                ((warpN + g * 8 + (lane & 7)) * KROW + (lane >> 3) * 4) * 4;
            ldsm4(bhf[g], base);
            ldsm4(blf[g], base + 10240);
        }
        #pragma unroll
        for (int kf = 0; kf < 2; kf++) {
            uint32_t ah[4][4], al[4][4];
            #pragma unroll
            for (int mt = 0; mt < 4; mt++) {
                const uint32_t off = sb +
                    ((warpM + mt * 16 + (lane & 15)) * KROW + kf * 8 + (lane >> 4) * 4) * 4;
                ldsm4(ah[mt], off);
                ldsm4(al[mt], off + 10240);
            }
            #pragma unroll
            for (int mt = 0; mt < 4; mt++)
                #pragma unroll
                for (int nt = 0; nt < 4; nt++) {
                    const uint32_t b0 = bhf[nt][kf * 2], b1 = bhf[nt][kf * 2 + 1];
                    const uint32_t c0 = blf[nt][kf * 2], c1 = blf[nt][kf * 2 + 1];
                    mma16816(cfr[mt][nt], ah[mt], b0, b1);
                    mma16816(cfr[mt][nt], al[mt], b0, b1);
                    mma16816(cfr[mt][nt], ah[mt], c0, c1);
                }
        }
        __syncthreads();
        if (s + 2 < 4) issue(s + 2);
    }

    #pragma unroll
    for (int mt = 0; mt < 4; mt++) {
        const size_t mA = (size_t)(m0 + warpM + mt * 16 + lr);
        const size_t mB = mA + 8;
        #pragma unroll
        for (int nt = 0; nt < 4; nt++) {
            const int j = n0 + warpN + nt * 8 + 2 * lc;
            const float b0v = bo[j], b1v = bo[j + 1];
            const float2 xa = *(const float2*)&x[mA * C + j];
            const float2 xb = *(const float2*)&x[mB * C + j];
            *(float2*)&out[mA * C + j] =
                make_float2(xa.x + cfr[mt][nt][0] + b0v, xa.y + cfr[mt][nt][1] + b1v);
            *(float2*)&out[mB * C + j] =
                make_float2(xb.x + cfr[mt][nt][2] + b0v, xb.y + cfr[mt][nt][3] + b1v);
        }
    }
}

// ---------------------------------------------------------------------------
extern "C" void kernel_launch(void* const* d_in, const int* in_sizes, int n_in,
                              void* d_out, int out_size)
{
    const float* x  = (const float*)d_in[0];
    const float* Wf = (const float*)d_in[1];
    const float* bf = (const float*)d_in[2];
    const float* Wg = (const float*)d_in[3];
    const float* bg = (const float*)d_in[4];
    const float* Wh = (const float*)d_in[5];
    const float* bh = (const float*)d_in[6];
    const float* Wo = (const float*)d_in[7];
    const float* bo = (const float*)d_in[8];
    float* out = (float*)d_out;

    presplit_x_kernel<<<2048, 256>>>(x);
    presplit_w_kernel<<<320, 256>>>(Wf, Wg, Wh, Wo);

    const int smem_proj = 2 * PBUF;
    cudaFuncSetAttribute(proj_kernel,
                         cudaFuncAttributeMaxDynamicSharedMemorySize, smem_proj);
    proj_kernel<<<dim3(M_TOTAL / 128, 3), 256, smem_proj>>>(bf, bg, bh);

    const int smem_attn = 3 * BUFB;   // 165888
    cudaFuncSetAttribute(attn_kernel,
                         cudaFuncAttributeMaxDynamicSharedMemorySize, smem_attn);
    attn_kernel<<<dim3(HW / TQ, BATCH), 256, smem_attn>>>();

    const int smem_op = 2 * OBUF;
    cudaFuncSetAttribute(outproj_kernel,
                         cudaFuncAttributeMaxDynamicSharedMemorySize, smem_op);
    outproj_kernel<<<dim3(M_TOTAL / 128, C / 128), 256, smem_op>>>(x, bo, out);
}

// round 14
// speedup vs baseline: 1.1002x; 1.1002x over previous
#include <cuda_runtime.h>
#include <cuda_fp16.h>
#include <cstdint>

#define BATCH 16
#define HW    4096
#define C     256
#define D     32
#define DV    128
#define M_TOTAL (BATCH * HW)

#define TQ 64          // q rows per block (4 warps x 16)
#define TK 128
#define NTILES (HW / TK)
#define LOG2E 1.4426950408889634f

#define KROW 20     // attn K smem row stride (u32)
#define VROW 68     // attn V smem row stride (u32)
#define BUFB 55296  // attn smem bytes per buffer (Kh 10240 + Kl 10240 + V 34816)

// ---- device scratch (no allocation allowed) ----
__device__ __align__(16) __half d_xh [(size_t)M_TOTAL * C];   // x hi
__device__ __align__(16) __half d_xl [(size_t)M_TOTAL * C];   // x lo
__device__ __align__(16) __half d_wph[192 * C];               // proj W hi [n][k]
__device__ __align__(16) __half d_wpl[192 * C];               // proj W lo [n][k]
__device__ __align__(16) __half d_woh[C * DV];                // Wo hi [n][k]
__device__ __align__(16) __half d_wol[C * DV];                // Wo lo [n][k]
__device__ __align__(16) __half d_fh [(size_t)M_TOTAL * D];   // K hi
__device__ __align__(16) __half d_fl [(size_t)M_TOTAL * D];   // K lo
__device__ float                d_g  [(size_t)M_TOTAL * D];   // Q fp32
__device__ __align__(16) __half d_hn [(size_t)M_TOTAL * DV];  // V fp16 [m][dv]
__device__ __align__(16) __half d_obh[(size_t)M_TOTAL * DV];  // O hi
__device__ __align__(16) __half d_obl[(size_t)M_TOTAL * DV];  // O lo

// ---- helpers ----
__device__ __forceinline__ uint32_t packh2(float lo, float hi) {
    uint32_t r;
    asm("cvt.rn.f16x2.f32 %0, %1, %2;" : "=r"(r) : "f"(hi), "f"(lo));
    return r;
}
__device__ __forceinline__ void split2(float v0, float v1, uint32_t& hi, uint32_t& lo) {
    hi = packh2(v0, v1);
    __half2 h = *reinterpret_cast<__half2*>(&hi);
    float2 f = __half22float2(h);
    lo = packh2(v0 - f.x, v1 - f.y);
}
__device__ __forceinline__ void mma16816(float* c, const uint32_t* a,
                                         uint32_t b0, uint32_t b1) {
    asm volatile(
        "mma.sync.aligned.m16n8k16.row.col.f32.f16.f16.f32 "
        "{%0,%1,%2,%3}, {%4,%5,%6,%7}, {%8,%9}, {%0,%1,%2,%3};"
        : "+f"(c[0]), "+f"(c[1]), "+f"(c[2]), "+f"(c[3])
        : "r"(a[0]), "r"(a[1]), "r"(a[2]), "r"(a[3]), "r"(b0), "r"(b1));
}
__device__ __forceinline__ void cp16(uint32_t sdst, const void* gsrc) {
    asm volatile("cp.async.cg.shared.global [%0], [%1], 16;" :: "r"(sdst), "l"(gsrc));
}
__device__ __forceinline__ void ldsm4(uint32_t* r, uint32_t a) {
    asm volatile("ldmatrix.sync.aligned.m8n8.x4.shared.b16 {%0,%1,%2,%3}, [%4];"
                 : "=r"(r[0]), "=r"(r[1]), "=r"(r[2]), "=r"(r[3]) : "r"(a));
}
__device__ __forceinline__ void ldsm4t(uint32_t* r, uint32_t a) {
    asm volatile("ldmatrix.sync.aligned.m8n8.x4.trans.shared.b16 {%0,%1,%2,%3}, [%4];"
                 : "=r"(r[0]), "=r"(r[1]), "=r"(r[2]), "=r"(r[3]) : "r"(a));
}

// ---------------------------------------------------------------------------
// Pre-split: x -> fp16 hi/lo
// ---------------------------------------------------------------------------
__global__ __launch_bounds__(256) void presplit_x_kernel(const float* __restrict__ x) {
    const size_t NX4 = (size_t)M_TOTAL * C / 4;
    const size_t stride = (size_t)gridDim.x * blockDim.x;
    for (size_t i = (size_t)blockIdx.x * blockDim.x + threadIdx.x; i < NX4; i += stride) {
        float4 v = ((const float4*)x)[i];
        uint32_t h0, l0, h1, l1;
        split2(v.x, v.y, h0, l0);
        split2(v.z, v.w, h1, l1);
        ((uint2*)d_xh)[i] = make_uint2(h0, h1);
        ((uint2*)d_xl)[i] = make_uint2(l0, l1);
    }
}

__global__ __launch_bounds__(256) void presplit_w_kernel(
    const float* __restrict__ Wf, const float* __restrict__ Wg,
    const float* __restrict__ Wh, const float* __restrict__ Wo)
{
    const int t = blockIdx.x * blockDim.x + threadIdx.x;
    if (t < 192 * 256) {
        const int n = t >> 8, k = t & 255;
        const float v = (n < 32) ? Wf[k * 32 + n]
                      : (n < 64) ? Wg[k * 32 + (n - 32)]
                                 : Wh[k * 128 + (n - 64)];
        const __half hv = __float2half_rn(v);
        d_wph[t] = hv;
        d_wpl[t] = __float2half_rn(v - __half2float(hv));
    }
    const int t2 = t - 192 * 256;
    if (t2 >= 0 && t2 < 256 * 128) {
        const int n = t2 >> 7, k = t2 & 127;
        const float v = Wo[k * 256 + n];
        const __half hv = __float2half_rn(v);
        d_woh[t2] = hv;
        d_wol[t2] = __float2half_rn(v - __half2float(hv));
    }
}

// ---------------------------------------------------------------------------
// Flash attention: TQ=64, 128 threads (4 warps), 2 blocks/SM for inter-block
// pipeline desync. R7 full-tile structure, fp16 HMMA, register-resident P.
// ---------------------------------------------------------------------------
__global__ __launch_bounds__(128, 2) void attn_kernel() {
    extern __shared__ char sm[];
    const uint32_t smem_u32 = (uint32_t)__cvta_generic_to_shared(sm);

    const int b   = blockIdx.y;
    const int q0  = blockIdx.x * TQ;
    const int tid = threadIdx.x;
    const int w   = tid >> 5;          // 0..3
    const int lane = tid & 31;
    const int lr  = lane >> 2;
    const int lc  = lane & 3;

    // Q fragments (fp16 hi/lo, pre-scaled by log2e)
    uint32_t qh[2][4], ql[2][4];
    {
        const float* gq = d_g + ((size_t)b * HW + q0 + w * 16) * D;
        #pragma unroll
        for (int ks = 0; ks < 2; ks++) {
            #pragma unroll
            for (int r = 0; r < 4; r++) {
                const int row = (r & 1) ? (lr + 8) : lr;
                const int col = ks * 16 + ((r & 2) ? 8 : 0) + 2 * lc;
                const float v0 = gq[row * D + col]     * LOG2E;
                const float v1 = gq[row * D + col + 1] * LOG2E;
                split2(v0, v1, qh[ks][r], ql[ks][r]);
            }
        }
    }

    float o[16][4];
    #pragma unroll
    for (int nt = 0; nt < 16; nt++)
        o[nt][0] = o[nt][1] = o[nt][2] = o[nt][3] = 0.f;
    float lsum[4] = {0.f, 0.f, 0.f, 0.f};
    float mrow0 = -1e30f, mrow1 = -1e30f;

    auto issue_tile = [&](int t) {
        const uint32_t sb = smem_u32 + (t & 1) * BUFB;
        const int k0 = t * TK;
        #pragma unroll
        for (int i = 0; i < 8; i++) {                  // K hi+lo: 1024 chunks
            const int idx = tid + 128 * i;
            const int arr = idx >> 9;
            const int row = (idx >> 2) & 127;
            const int c   = idx & 3;
            const __half* g = (arr ? d_fl : d_fh)
                              + ((size_t)(b * HW + k0 + row)) * D + c * 8;
            cp16(sb + arr * 10240 + row * 80 + c * 16, g);
        }
        #pragma unroll
        for (int i = 0; i < 16; i++) {                 // V: 2048 chunks
            const int idx = tid + 128 * i;
            const int row = idx >> 4;
            const int c   = idx & 15;
            const __half* g = d_hn + ((size_t)(b * HW + k0 + row)) * DV + c * 8;
            cp16(sb + 20480 + row * 272 + c * 16, g);
        }
        asm volatile("cp.async.commit_group;");
    };

    const uint32_t koff = ((lane & 7) * KROW + (lane >> 3) * 4) * 4;
    const uint32_t voff = ((lane & 15) * VROW) * 4 + (lane >> 4) * 16;

    issue_tile(0);

    #pragma unroll 1
    for (int t = 0; t < NTILES; t++) {
        if (t + 1 < NTILES) {
            issue_tile(t + 1);
            asm volatile("cp.async.wait_group 1;");
        } else {
            asm volatile("cp.async.wait_group 0;");
        }
        __syncthreads();

        const uint32_t sb = smem_u32 + (t & 1) * BUFB;
        const uint32_t khb = sb + koff;
        const uint32_t vb  = sb + 20480 + voff;

        // ---- S = Q K^T (2-term split) ----
        float s[16][4];
        #pragma unroll
        for (int nt = 0; nt < 16; nt++) {
            uint32_t kh[4], kl[4];
            ldsm4(kh, khb + nt * 640);
            ldsm4(kl, khb + 10240 + nt * 640);
            s[nt][0] = s[nt][1] = s[nt][2] = s[nt][3] = 0.f;
            mma16816(s[nt], qh[0], kh[0], kh[1]);
            mma16816(s[nt], ql[0], kh[0], kh[1]);
            mma16816(s[nt], qh[0], kl[0], kl[1]);
            mma16816(s[nt], qh[1], kh[2], kh[3]);
            mma16816(s[nt], ql[1], kh[2], kh[3]);
            mma16816(s[nt], qh[1], kl[2], kl[3]);
        }

        // ---- online softmax (log2 domain) ----
        float mx0 = fmaxf(s[0][0], s[0][1]);
        float mx1 = fmaxf(s[0][2], s[0][3]);
        #pragma unroll
        for (int nt = 1; nt < 16; nt++) {
            mx0 = fmaxf(mx0, fmaxf(s[nt][0], s[nt][1]));
            mx1 = fmaxf(mx1, fmaxf(s[nt][2], s[nt][3]));
        }
        mx0 = fmaxf(mx0, __shfl_xor_sync(0xffffffffu, mx0, 1));
        mx0 = fmaxf(mx0, __shfl_xor_sync(0xffffffffu, mx0, 2));
        mx1 = fmaxf(mx1, __shfl_xor_sync(0xffffffffu, mx1, 1));
        mx1 = fmaxf(mx1, __shfl_xor_sync(0xffffffffu, mx1, 2));

        const float mn0 = fmaxf(mrow0, mx0);
        const float mn1 = fmaxf(mrow1, mx1);
        const float corr0 = exp2f(mrow0 - mn0);
        const float corr1 = exp2f(mrow1 - mn1);
        mrow0 = mn0; mrow1 = mn1;

        // p = exp2(s - mn) in packed fp16
        uint32_t pa[8][4];
        #pragma unroll
        for (int nt = 0; nt < 16; nt++) {
            const uint32_t d01 = packh2(s[nt][0] - mn0, s[nt][1] - mn0);
            const uint32_t d23 = packh2(s[nt][2] - mn1, s[nt][3] - mn1);
            uint32_t p01, p23;
            asm("ex2.approx.f16x2 %0, %1;" : "=r"(p01) : "r"(d01));
            asm("ex2.approx.f16x2 %0, %1;" : "=r"(p23) : "r"(d23));
            pa[nt >> 1][(nt & 1) ? 2 : 0] = p01;
            pa[nt >> 1][(nt & 1) ? 3 : 1] = p23;
        }

        lsum[0] *= corr0; lsum[2] *= corr1;
        #pragma unroll
        for (int nt = 0; nt < 16; nt++) {
            o[nt][0] *= corr0; o[nt][1] *= corr0;
            o[nt][2] *= corr1; o[nt][3] *= corr1;
        }

        // ---- O += P V ----
        const uint32_t ONES = 0x3C003C00u;
        #pragma unroll
        for (int ks = 0; ks < 8; ks++) {
            mma16816(lsum, pa[ks], ONES, ONES);
            const uint32_t vrow = vb + ks * 4352;
            #pragma unroll
            for (int ntp = 0; ntp < 8; ntp++) {
                uint32_t v[4];
                ldsm4t(v, vrow + ntp * 32);
                mma16816(o[2 * ntp],     pa[ks], v[0], v[1]);
                mma16816(o[2 * ntp + 1], pa[ks], v[2], v[3]);
            }
        }
        __syncthreads();
    }

    // ---- normalize + store fp16 hi/lo ----
    const float inv0 = 1.f / lsum[0];
    const float inv1 = 1.f / lsum[2];
    uint32_t* goh = (uint32_t*)d_obh + ((size_t)b * HW + q0 + w * 16) * 64;
    uint32_t* gol = (uint32_t*)d_obl + ((size_t)b * HW + q0 + w * 16) * 64;
    #pragma unroll
    for (int nt = 0; nt < 16; nt++) {
        uint32_t hi, lo;
        split2(o[nt][0] * inv0, o[nt][1] * inv0, hi, lo);
        goh[lr * 64 + nt * 4 + lc] = hi;
        gol[lr * 64 + nt * 4 + lc] = lo;
        split2(o[nt][2] * inv1, o[nt][3] * inv1, hi, lo);
        goh[(lr + 8) * 64 + nt * 4 + lc] = hi;
        gol[(lr + 8) * 64 + nt * 4 + lc] = lo;
    }
}

// ---------------------------------------------------------------------------
// proj: [65536,256] @ [256,192], fp16 3-term split, cp.async double-buffered.
// ---------------------------------------------------------------------------
#define PBUF 30720
__global__ __launch_bounds__(256, 2) void proj_kernel(
    const float* __restrict__ bf, const float* __restrict__ bg,
    const float* __restrict__ bh)
{
    extern __shared__ char smp[];
    const uint32_t sb0 = (uint32_t)__cvta_generic_to_shared(smp);

    const int m0 = blockIdx.x * 128;
    const int by = blockIdx.y;
    const int n0 = by * 64;
    const int tid = threadIdx.x;
    const int lane = tid & 31;
    const int w = tid >> 5;
    const int warpM = (w >> 1) * 32;
    const int warpN = (w & 1) * 32;
    const int lr = lane >> 2, lc = lane & 3;

    auto issue = [&](int s) {
        const uint32_t sb = sb0 + (s & 1) * PBUF;
        const int k0 = s * 32;
        #pragma unroll
        for (int i = 0; i < 4; i++) {
            const int idx = tid + 256 * i;
            const int arr = idx >> 9;
            const int row = (idx >> 2) & 127;
            const int c   = idx & 3;
            const __half* g = (arr ? d_xl : d_xh) + (size_t)(m0 + row) * C + k0 + c * 8;
            cp16(sb + arr * 10240 + row * 80 + c * 16, g);
        }
        #pragma unroll
        for (int i = 0; i < 2; i++) {
            const int idx = tid + 256 * i;
            const int arr = idx >> 8;
            const int row = (idx >> 2) & 63;
            const int c   = idx & 3;
            const __half* g = (arr ? d_wpl : d_wph) + (size_t)(n0 + row) * C + k0 + c * 8;
            cp16(sb + 20480 + arr * 5120 + row * 80 + c * 16, g);
        }
        asm volatile("cp.async.commit_group;");
    };

    float cfr[2][4][4];
    #pragma unroll
    for (int mt = 0; mt < 2; mt++)
        #pragma unroll
        for (int nt = 0; nt < 4; nt++)
            cfr[mt][nt][0] = cfr[mt][nt][1] = cfr[mt][nt][2] = cfr[mt][nt][3] = 0.f;

    issue(0); issue(1);

    #pragma unroll 1
    for (int s = 0; s < 8; s++) {
        if (s < 7) asm volatile("cp.async.wait_group 1;");
        else       asm volatile("cp.async.wait_group 0;");
        __syncthreads();

        const uint32_t sb = sb0 + (s & 1) * PBUF;

        uint32_t bhf[4][4], blf[4][4];
        #pragma unroll
        for (int g = 0; g < 4; g++) {
            const uint32_t base = sb + 20480 +
                ((warpN + g * 8 + (lane & 7)) * KROW + (lane >> 3) * 4) * 4;
            ldsm4(bhf[g], base);
            ldsm4(blf[g], base + 5120);
        }
        #pragma unroll
        for (int kf = 0; kf < 2; kf++) {
            uint32_t ah[2][4], al[2][4];
            #pragma unroll
            for (int mt = 0; mt < 2; mt++) {
                const uint32_t off = sb +
                    ((warpM + mt * 16 + (lane & 15)) * KROW + kf * 8 + (lane >> 4) * 4) * 4;
                ldsm4(ah[mt], off);
                ldsm4(al[mt], off + 10240);
            }
            #pragma unroll
            for (int mt = 0; mt < 2; mt++)
                #pragma unroll
                for (int nt = 0; nt < 4; nt++) {
                    const uint32_t b0 = bhf[nt][kf * 2], b1 = bhf[nt][kf * 2 + 1];
                    const uint32_t c0 = blf[nt][kf * 2], c1 = blf[nt][kf * 2 + 1];
                    mma16816(cfr[mt][nt], ah[mt], b0, b1);
                    mma16816(cfr[mt][nt], al[mt], b0, b1);
                    mma16816(cfr[mt][nt], ah[mt], c0, c1);
                }
        }
        __syncthreads();
        if (s + 2 < 8) issue(s + 2);
    }

    #pragma unroll
    for (int mt = 0; mt < 2; mt++) {
        const size_t mA = (size_t)(m0 + warpM + mt * 16 + lr);
        const size_t mB = mA + 8;
        #pragma unroll
        for (int nt = 0; nt < 4; nt++) {
            const int jl = warpN + nt * 8 + 2 * lc;
            const float c0 = cfr[mt][nt][0], c1 = cfr[mt][nt][1];
            const float c2 = cfr[mt][nt][2], c3 = cfr[mt][nt][3];
            if (by == 0) {
                if (jl < 32) {
                    const float b0v = bf[jl], b1v = bf[jl + 1];
                    uint32_t hi, lo;
                    split2(c0 + b0v, c1 + b1v, hi, lo);
                    ((uint32_t*)d_fh)[mA * 16 + (jl >> 1)] = hi;
                    ((uint32_t*)d_fl)[mA * 16 + (jl >> 1)] = lo;
                    split2(c2 + b0v, c3 + b1v, hi, lo);
                    ((uint32_t*)d_fh)[mB * 16 + (jl >> 1)] = hi;
                    ((uint32_t*)d_fl)[mB * 16 + (jl >> 1)] = lo;
                } else {
                    const int jj = jl - 32;
                    const float b0v = bg[jj], b1v = bg[jj + 1];
                    *(float2*)&d_g[mA * D + jj] = make_float2(c0 + b0v, c1 + b1v);
                    *(float2*)&d_g[mB * D + jj] = make_float2(c2 + b0v, c3 + b1v);
                }
            } else {
                const int dv = (by - 1) * 64 + jl;
                const float b0v = bh[dv], b1v = bh[dv + 1];
                ((uint32_t*)d_hn)[mA * 64 + (dv >> 1)] = packh2(c0 + b0v, c1 + b1v);
                ((uint32_t*)d_hn)[mB * 64 + (dv >> 1)] = packh2(c2 + b0v, c3 + b1v);
            }
        }
    }
}

// ---------------------------------------------------------------------------
// outproj: out = x + O @ Wo + bo, fp16 3-term, fully double-buffered.
// ---------------------------------------------------------------------------
#define OBUF 40960
__global__ __launch_bounds__(256, 1) void outproj_kernel(
    const float* __restrict__ x,
    const float* __restrict__ bo,
    float* __restrict__ out)
{
    extern __shared__ char smo[];
    const uint32_t sb0 = (uint32_t)__cvta_generic_to_shared(smo);

    const int m0 = blockIdx.x * 128;
    const int n0 = blockIdx.y * 128;
    const int tid = threadIdx.x;
    const int lane = tid & 31;
    const int w = tid >> 5;
    const int warpM = (w >> 2) * 64;
    const int warpN = (w & 3) * 32;
    const int lr = lane >> 2, lc = lane & 3;

    auto issue = [&](int s) {
        const uint32_t sb = sb0 + (s & 1) * OBUF;
        const int k0 = s * 32;
        #pragma unroll
        for (int i = 0; i < 4; i++) {
            const int idx = tid + 256 * i;
            const int arr = idx >> 9;
            const int row = (idx >> 2) & 127;
            const int c   = idx & 3;
            const __half* g = (arr ? d_obl : d_obh) + (size_t)(m0 + row) * DV + k0 + c * 8;
            cp16(sb + arr * 10240 + row * 80 + c * 16, g);
        }
        #pragma unroll
        for (int i = 0; i < 4; i++) {
            const int idx = tid + 256 * i;
            const int arr = idx >> 9;
            const int row = (idx >> 2) & 127;
            const int c   = idx & 3;
            const __half* g = (arr ? d_wol : d_woh) + (size_t)(n0 + row) * DV + k0 + c * 8;
            cp16(sb + 20480 + arr * 10240 + row * 80 + c * 16, g);
        }
        asm volatile("cp.async.commit_group;");
    };

    float cfr[4][4][4];
    #pragma unroll
    for (int mt = 0; mt < 4; mt++)
        #pragma unroll
        for (int nt = 0; nt < 4; nt++)
            cfr[mt][nt][0] = cfr[mt][nt][1] = cfr[mt][nt][2] = cfr[mt][nt][3] = 0.f;

    issue(0); issue(1);

    #pragma unroll 1
    for (int s = 0; s < 4; s++) {
        if (s < 3) asm volatile("cp.async.wait_group 1;");
        else       asm volatile("cp.async.wait_group 0;");
        __syncthreads();

        const uint32_t sb = sb0 + (s & 1) * OBUF;

        uint32_t bhf[4][4], blf[4][4];
        #pragma unroll
        for (int g = 0; g < 4; g++) {
            const uint32_t base = sb + 20480 +
                ((warpN + g * 8 + (lane & 7)) * KROW + (lane >> 3) * 4) * 4;
            ldsm4(bhf[g], base);
            ldsm4(blf[g], base + 10240);
        }
        #pragma unroll
        for (int kf = 0; kf < 2; kf++) {
            uint32_t ah[4][4], al[4][4];
            #pragma unroll
            for (int mt = 0; mt < 4; mt++) {
                const uint32_t off = sb +
                    ((warpM + mt * 16 + (lane & 15)) * KROW + kf * 8 + (lane >> 4) * 4) * 4;
                ldsm4(ah[mt], off);
                ldsm4(al[mt], off + 10240);
            }
            #pragma unroll
            for (int mt = 0; mt < 4; mt++)
                #pragma unroll
                for (int nt = 0; nt < 4; nt++) {
                    const uint32_t b0 = bhf[nt][kf * 2], b1 = bhf[nt][kf * 2 + 1];
                    const uint32_t c0 = blf[nt][kf * 2], c1 = blf[nt][kf * 2 + 1];
                    mma16816(cfr[mt][nt], ah[mt], b0, b1);
                    mma16816(cfr[mt][nt], al[mt], b0, b1);
                    mma16816(cfr[mt][nt], ah[mt], c0, c1);
                }
        }
        __syncthreads();
        if (s + 2 < 4) issue(s + 2);
    }

    #pragma unroll
    for (int mt = 0; mt < 4; mt++) {
        const size_t mA = (size_t)(m0 + warpM + mt * 16 + lr);
        const size_t mB = mA + 8;
        #pragma unroll
        for (int nt = 0; nt < 4; nt++) {
            const int j = n0 + warpN + nt * 8 + 2 * lc;
            const float b0v = bo[j], b1v = bo[j + 1];
            const float2 xa = *(const float2*)&x[mA * C + j];
            const float2 xb = *(const float2*)&x[mB * C + j];
            *(float2*)&out[mA * C + j] =
                make_float2(xa.x + cfr[mt][nt][0] + b0v, xa.y + cfr[mt][nt][1] + b1v);
            *(float2*)&out[mB * C + j] =
                make_float2(xb.x + cfr[mt][nt][2] + b0v, xb.y + cfr[mt][nt][3] + b1v);
        }
    }
}

// ---------------------------------------------------------------------------
extern "C" void kernel_launch(void* const* d_in, const int* in_sizes, int n_in,
                              void* d_out, int out_size)
{
    const float* x  = (const float*)d_in[0];
    const float* Wf = (const float*)d_in[1];
    const float* bf = (const float*)d_in[2];
    const float* Wg = (const float*)d_in[3];
    const float* bg = (const float*)d_in[4];
    const float* Wh = (const float*)d_in[5];
    const float* bh = (const float*)d_in[6];
    const float* Wo = (const float*)d_in[7];
    const float* bo = (const float*)d_in[8];
    float* out = (float*)d_out;

    presplit_x_kernel<<<2048, 256>>>(x);
    presplit_w_kernel<<<320, 256>>>(Wf, Wg, Wh, Wo);

    const int smem_proj = 2 * PBUF;
    cudaFuncSetAttribute(proj_kernel,
                         cudaFuncAttributeMaxDynamicSharedMemorySize, smem_proj);
    proj_kernel<<<dim3(M_TOTAL / 128, 3), 256, smem_proj>>>(bf, bg, bh);

    const int smem_attn = 2 * BUFB;   // 110592 per block; 2 blocks/SM
    cudaFuncSetAttribute(attn_kernel,
                         cudaFuncAttributeMaxDynamicSharedMemorySize, smem_attn);
    attn_kernel<<<dim3(HW / TQ, BATCH), 128, smem_attn>>>();

    const int smem_op = 2 * OBUF;
    cudaFuncSetAttribute(outproj_kernel,
                         cudaFuncAttributeMaxDynamicSharedMemorySize, smem_op);
    outproj_kernel<<<dim3(M_TOTAL / 128, C / 128), 256, smem_op>>>(x, bo, out);
}